// round 7
// baseline (speedup 1.0000x reference)
#include <cuda_runtime.h>
#include <cstddef>

#define KCODES 1024
#define DDIM   256
#define NPIX   65536
#define BPX    32
#define TKC    64
#define DCH    32
#define SE2    68
#define THREADS 256

__device__ float g_enorm[KCODES];
__device__ float g_A[NPIX];

// ---------------------------------------------------------------------------
// Emulated XLA-CPU row sum of squares: squares rounded individually
// (fl(x*x)), 8 mod-8 partial chains (VF=4 x IC=2), combine
// m_l = S_l + S_{l+4}, then pairwise tree (m0+m1)+(m2+m3).
// ---------------------------------------------------------------------------
__device__ __forceinline__ float sumsq_emul(const float* x, long stride) {
    float S[8];
#pragma unroll
    for (int l = 0; l < 8; l++) S[l] = 0.f;
    for (int t = 0; t < DDIM / 8; t++) {
#pragma unroll
        for (int l = 0; l < 8; l++) {
            float v = x[(long)(8 * t + l) * stride];
            S[l] = __fadd_rn(S[l], __fmul_rn(v, v));
        }
    }
    float m0 = __fadd_rn(S[0], S[4]);
    float m1 = __fadd_rn(S[1], S[5]);
    float m2 = __fadd_rn(S[2], S[6]);
    float m3 = __fadd_rn(S[3], S[7]);
    return __fadd_rn(__fadd_rn(m0, m1), __fadd_rn(m2, m3));
}

// ---- per-code ||e_k||^2, emulated order -----------------------------------
__global__ void enorm_kernel(const float* __restrict__ emb) {
    int c = blockIdx.x * blockDim.x + threadIdx.x;
    if (c < KCODES) g_enorm[c] = sumsq_emul(emb + (size_t)c * DDIM, 1);
}

// ---- per-pixel ||z_n||^2, emulated order (strided reads, coalesced) -------
__global__ void anorm_kernel(const float* __restrict__ z) {
    int p = blockIdx.x * blockDim.x + threadIdx.x;
    if (p < NPIX) {
        const float* zp = z + (size_t)(p >> 12) * (DDIM * 4096) + (p & 4095);
        g_A[p] = sumsq_emul(zp, 4096);
    }
}

// ---------------------------------------------------------------------------
// Main: block = 32 pixels x 1024 codes. Dots accumulated in fp64 (correctly
// rounded to f32 once), then the reference's exact fp32 formula:
//   dist = fl( fl(A - 2*Mf) + en ),  argmin ascending k, strict '<'.
// Output written as FLOAT (comparator dtype).
// ---------------------------------------------------------------------------
__global__ __launch_bounds__(THREADS, 1)
void vq_kernel(const float* __restrict__ z, const float* __restrict__ emb,
               float* __restrict__ out) {
    __shared__ float z_s[DDIM * BPX];   // 32 KB [d][px]
    __shared__ float e_s[DCH * SE2];    // 8.5 KB [d][code]
    __shared__ float en_s[KCODES];      // 4 KB
    __shared__ float A_s[BPX];

    const int tid = threadIdx.x;
    const int tx  = tid & 15;           // pixel pair
    const int ty  = tid >> 4;           // code group

    const int n0 = blockIdx.x * BPX;
    const float* zbase = z + (size_t)(n0 >> 12) * (DDIM * 4096) + (n0 & 4095);

#pragma unroll
    for (int i = tid; i < DDIM * BPX; i += THREADS) {
        int d = i >> 5, p = i & 31;
        z_s[i] = zbase[(size_t)d * 4096 + p];
    }
    for (int i = tid; i < KCODES; i += THREADS) en_s[i] = g_enorm[i];
    if (tid < BPX) A_s[tid] = g_A[n0 + tid];
    __syncthreads();

    const float A0 = A_s[tx * 2];
    const float A1 = A_s[tx * 2 + 1];
    float bv0 = 3.4e38f, bv1 = 3.4e38f;
    int   bi0 = 0,        bi1 = 0;

    for (int k0 = 0; k0 < KCODES; k0 += TKC) {
        double acc0[4] = {0.0, 0.0, 0.0, 0.0};
        double acc1[4] = {0.0, 0.0, 0.0, 0.0};

        for (int d0 = 0; d0 < DDIM; d0 += DCH) {
            __syncthreads();
            {   // e chunk transposed: e_s[d][k]
                int code = tid >> 2;
                int q    = tid & 3;
                const float* erow = emb + (size_t)(k0 + code) * DDIM + d0;
#pragma unroll
                for (int j = 0; j < 2; j++) {
                    int d4 = q + 4 * j;
                    float4 v = *(const float4*)(erow + 4 * d4);
                    e_s[(4 * d4 + 0) * SE2 + code] = v.x;
                    e_s[(4 * d4 + 1) * SE2 + code] = v.y;
                    e_s[(4 * d4 + 2) * SE2 + code] = v.z;
                    e_s[(4 * d4 + 3) * SE2 + code] = v.w;
                }
            }
            __syncthreads();

            const float* zp = z_s + (size_t)d0 * BPX + tx * 2;
#pragma unroll 4
            for (int d = 0; d < DCH; d++) {
                float2 zz = *(const float2*)(zp + d * BPX);
                float4 ee = *(const float4*)(e_s + d * SE2 + ty * 4);
                double zx = (double)zz.x, zy = (double)zz.y;
                double e0 = (double)ee.x, e1 = (double)ee.y;
                double e2 = (double)ee.z, e3 = (double)ee.w;
                acc0[0] = fma(zx, e0, acc0[0]);
                acc0[1] = fma(zx, e1, acc0[1]);
                acc0[2] = fma(zx, e2, acc0[2]);
                acc0[3] = fma(zx, e3, acc0[3]);
                acc1[0] = fma(zy, e0, acc1[0]);
                acc1[1] = fma(zy, e1, acc1[1]);
                acc1[2] = fma(zy, e2, acc1[2]);
                acc1[3] = fma(zy, e3, acc1[3]);
            }
        }

#pragma unroll
        for (int c = 0; c < 4; c++) {
            int k = k0 + ty * 4 + c;
            float en = en_s[k];
            float M0 = (float)acc0[c];          // correctly rounded dot
            float M1 = (float)acc1[c];
            float d0v = __fadd_rn(__fsub_rn(A0, __fmul_rn(2.0f, M0)), en);
            float d1v = __fadd_rn(__fsub_rn(A1, __fmul_rn(2.0f, M1)), en);
            if (d0v < bv0) { bv0 = d0v; bi0 = k; }
            if (d1v < bv1) { bv1 = d1v; bi1 = k; }
        }
    }

    // cross-thread reduction per pixel; tie -> smallest index
    __syncthreads();
    float* rv = e_s;                 // [32][17] floats
    int*   ri = (int*)(e_s + 544);   // [32][17] ints
    rv[(tx * 2 + 0) * 17 + ty] = bv0;  ri[(tx * 2 + 0) * 17 + ty] = bi0;
    rv[(tx * 2 + 1) * 17 + ty] = bv1;  ri[(tx * 2 + 1) * 17 + ty] = bi1;
    __syncthreads();
    if (tid < BPX) {
        float bv = rv[tid * 17];
        int   bi = ri[tid * 17];
#pragma unroll
        for (int t = 1; t < 16; t++) {
            float v = rv[tid * 17 + t];
            int   x = ri[tid * 17 + t];
            if (v < bv || (v == bv && x < bi)) { bv = v; bi = x; }
        }
        out[n0 + tid] = (float)bi;   // FLOAT output: comparator dtype
    }
}

// ---------------------------------------------------------------------------
extern "C" void kernel_launch(void* const* d_in, const int* in_sizes, int n_in,
                              void* d_out, int out_size) {
    // classify inputs by size in elements OR bytes, any order
    const float* z   = nullptr;
    const float* emb = nullptr;
    for (int i = 0; i < n_in; i++) {
        long s = (long)in_sizes[i];
        if (s == 16777216L || s == 67108864L)   z   = (const float*)d_in[i];
        else if (s == 262144L || s == 1048576L) emb = (const float*)d_in[i];
    }
    if (!z)   z   = (const float*)d_in[0];
    if (!emb) emb = (const float*)d_in[n_in > 1 ? 1 : 0];

    enorm_kernel<<<KCODES / 128, 128>>>(emb);
    anorm_kernel<<<NPIX / 128, 128>>>(z);
    vq_kernel<<<NPIX / BPX, THREADS>>>(z, emb, (float*)d_out);
}

// round 8
// speedup vs baseline: 16.3528x; 16.3528x over previous
#include <cuda_runtime.h>
#include <cstddef>

#define KCODES 1024
#define DDIM   256
#define NPIX   65536
#define BPX    32
#define TKC    64
#define DCH    32
#define SE2    68
#define THREADS 256
#define MARGIN  2e-4f

__device__ float g_enorm[KCODES];
__device__ float g_A[NPIX];
__device__ int   g_nflag;
__device__ int   g_flags[NPIX];

// ---------------------------------------------------------------------------
// Emulated reference row sum-of-squares (proven exact in R7):
// rounded squares, 8 mod-8 chains, m_l = S_l+S_{l+4}, pairwise tree.
// ---------------------------------------------------------------------------
__device__ __forceinline__ float sumsq_emul(const float* x, long stride) {
    float S[8];
#pragma unroll
    for (int l = 0; l < 8; l++) S[l] = 0.f;
    for (int t = 0; t < DDIM / 8; t++) {
#pragma unroll
        for (int l = 0; l < 8; l++) {
            float v = x[(long)(8 * t + l) * stride];
            S[l] = __fadd_rn(S[l], __fmul_rn(v, v));
        }
    }
    float m0 = __fadd_rn(S[0], S[4]);
    float m1 = __fadd_rn(S[1], S[5]);
    float m2 = __fadd_rn(S[2], S[6]);
    float m3 = __fadd_rn(S[3], S[7]);
    return __fadd_rn(__fadd_rn(m0, m1), __fadd_rn(m2, m3));
}

__global__ void reset_kernel() { if (threadIdx.x == 0) g_nflag = 0; }

__global__ void enorm_kernel(const float* __restrict__ emb) {
    int c = blockIdx.x * blockDim.x + threadIdx.x;
    if (c < KCODES) g_enorm[c] = sumsq_emul(emb + (size_t)c * DDIM, 1);
}

__global__ void anorm_kernel(const float* __restrict__ z) {
    int p = blockIdx.x * blockDim.x + threadIdx.x;
    if (p < NPIX) {
        const float* zp = z + (size_t)(p >> 12) * (DDIM * 4096) + (p & 4095);
        g_A[p] = sumsq_emul(zp, 4096);
    }
}

// ---------------------------------------------------------------------------
// Main pass: fp32 dots, best+second-best tracking, flag near-ties (< MARGIN).
// ---------------------------------------------------------------------------
__global__ __launch_bounds__(THREADS)
void vq_kernel(const float* __restrict__ z, const float* __restrict__ emb,
               float* __restrict__ out) {
    __shared__ float z_s[DDIM * BPX];   // 32 KB [d][px]
    __shared__ float e_s[DCH * SE2];    // 8.7 KB [d][code]
    __shared__ float en_s[KCODES];      // 4 KB
    __shared__ float A_s[BPX];

    const int tid = threadIdx.x;
    const int tx  = tid & 15;
    const int ty  = tid >> 4;

    const int n0 = blockIdx.x * BPX;
    const float* zbase = z + (size_t)(n0 >> 12) * (DDIM * 4096) + (n0 & 4095);

#pragma unroll
    for (int i = tid; i < DDIM * BPX; i += THREADS) {
        int d = i >> 5, p = i & 31;
        z_s[i] = zbase[(size_t)d * 4096 + p];
    }
    for (int i = tid; i < KCODES; i += THREADS) en_s[i] = g_enorm[i];
    if (tid < BPX) A_s[tid] = g_A[n0 + tid];
    __syncthreads();

    const float A0 = A_s[tx * 2];
    const float A1 = A_s[tx * 2 + 1];
    float bv0 = 3.4e38f, bv1 = 3.4e38f, sv0 = 3.4e38f, sv1 = 3.4e38f;
    int   bi0 = 0,        bi1 = 0;

    for (int k0 = 0; k0 < KCODES; k0 += TKC) {
        float acc0[4] = {0.f, 0.f, 0.f, 0.f};
        float acc1[4] = {0.f, 0.f, 0.f, 0.f};

        for (int d0 = 0; d0 < DDIM; d0 += DCH) {
            __syncthreads();
            {   // e chunk transposed: e_s[d][k]  (verbatim from R7)
                int code = tid >> 2;
                int q    = tid & 3;
                const float* erow = emb + (size_t)(k0 + code) * DDIM + d0;
#pragma unroll
                for (int j = 0; j < 2; j++) {
                    int d4 = q + 4 * j;
                    float4 v = *(const float4*)(erow + 4 * d4);
                    e_s[(4 * d4 + 0) * SE2 + code] = v.x;
                    e_s[(4 * d4 + 1) * SE2 + code] = v.y;
                    e_s[(4 * d4 + 2) * SE2 + code] = v.z;
                    e_s[(4 * d4 + 3) * SE2 + code] = v.w;
                }
            }
            __syncthreads();

            const float* zp = z_s + (size_t)d0 * BPX + tx * 2;
#pragma unroll 8
            for (int d = 0; d < DCH; d++) {
                float2 zz = *(const float2*)(zp + d * BPX);
                float4 ee = *(const float4*)(e_s + d * SE2 + ty * 4);
                acc0[0] = fmaf(zz.x, ee.x, acc0[0]);
                acc0[1] = fmaf(zz.x, ee.y, acc0[1]);
                acc0[2] = fmaf(zz.x, ee.z, acc0[2]);
                acc0[3] = fmaf(zz.x, ee.w, acc0[3]);
                acc1[0] = fmaf(zz.y, ee.x, acc1[0]);
                acc1[1] = fmaf(zz.y, ee.y, acc1[1]);
                acc1[2] = fmaf(zz.y, ee.z, acc1[2]);
                acc1[3] = fmaf(zz.y, ee.w, acc1[3]);
            }
        }

#pragma unroll
        for (int c = 0; c < 4; c++) {
            int k = k0 + ty * 4 + c;
            float en = en_s[k];
            float d0v = __fadd_rn(__fsub_rn(A0, __fmul_rn(2.0f, acc0[c])), en);
            float d1v = __fadd_rn(__fsub_rn(A1, __fmul_rn(2.0f, acc1[c])), en);
            if (d0v < bv0) { sv0 = bv0; bv0 = d0v; bi0 = k; }
            else if (d0v < sv0) sv0 = d0v;
            if (d1v < bv1) { sv1 = bv1; bv1 = d1v; bi1 = k; }
            else if (d1v < sv1) sv1 = d1v;
        }
    }

    // cross-thread merge of (best, idx, second)
    __syncthreads();
    float* rv = e_s;                   // [32][17]
    int*   ri = (int*)(e_s + 544);     // [32][17]
    float* rs = e_s + 1088;            // [32][17]
    rv[(tx*2+0)*17+ty] = bv0;  ri[(tx*2+0)*17+ty] = bi0;  rs[(tx*2+0)*17+ty] = sv0;
    rv[(tx*2+1)*17+ty] = bv1;  ri[(tx*2+1)*17+ty] = bi1;  rs[(tx*2+1)*17+ty] = sv1;
    __syncthreads();
    if (tid < BPX) {
        float bv = rv[tid*17];  int bi = ri[tid*17];  float sv = rs[tid*17];
#pragma unroll
        for (int t = 1; t < 16; t++) {
            float v = rv[tid*17+t]; int x = ri[tid*17+t]; float s2 = rs[tid*17+t];
            if (v < bv || (v == bv && x < bi)) { sv = fminf(bv, s2); bv = v; bi = x; }
            else sv = fminf(sv, v);
        }
        out[n0 + tid] = (float)bi;
        if (__fsub_rn(sv, bv) < MARGIN) {
            int idx = atomicAdd(&g_nflag, 1);
            g_flags[idx] = n0 + tid;
        }
    }
}

// ---------------------------------------------------------------------------
// Fix-up: flagged pixels re-solved with double-float (2Prod+2Sum) dots.
// fl(s+comp) ~ correctly rounded dot; then exact reference fp32 formula.
// ---------------------------------------------------------------------------
__global__ __launch_bounds__(256)
void fixup_kernel(const float* __restrict__ z, const float* __restrict__ emb,
                  float* __restrict__ out) {
    __shared__ float z_s[DDIM];
    __shared__ float bvs[256];
    __shared__ int   bis[256];

    for (int fi = blockIdx.x; fi < g_nflag; fi += gridDim.x) {
        int p = g_flags[fi];
        const float* zp = z + (size_t)(p >> 12) * (DDIM * 4096) + (p & 4095);
        __syncthreads();
        z_s[threadIdx.x] = zp[(size_t)threadIdx.x * 4096];
        __syncthreads();

        float A  = g_A[p];
        float bv = 3.4e38f;
        int   bi = 0;
#pragma unroll
        for (int c = 0; c < 4; c++) {
            int k = threadIdx.x + 256 * c;           // ascending per thread
            const float* er = emb + (size_t)k * DDIM;
            float s = 0.f, comp = 0.f;
            for (int d = 0; d < DDIM; d++) {
                float x = z_s[d], y = er[d];
                float pm = __fmul_rn(x, y);
                float e1 = fmaf(x, y, -pm);          // exact product error
                float t  = __fadd_rn(s, pm);         // 2Sum
                float vv = __fsub_rn(t, s);
                float e2 = __fadd_rn(__fsub_rn(s, __fsub_rn(t, vv)),
                                     __fsub_rn(pm, vv));
                s = t;
                comp = __fadd_rn(comp, __fadd_rn(e1, e2));
            }
            float M  = __fadd_rn(s, comp);           // ~correctly rounded
            float dv = __fadd_rn(__fsub_rn(A, __fmul_rn(2.0f, M)), g_enorm[k]);
            if (dv < bv) { bv = dv; bi = k; }
        }
        bvs[threadIdx.x] = bv; bis[threadIdx.x] = bi;
        __syncthreads();
        if (threadIdx.x == 0) {
            float b = bvs[0]; int i0 = bis[0];
            for (int t = 1; t < 256; t++) {
                float v = bvs[t]; int x = bis[t];
                if (v < b || (v == b && x < i0)) { b = v; i0 = x; }
            }
            out[p] = (float)i0;
        }
    }
}

// ---------------------------------------------------------------------------
extern "C" void kernel_launch(void* const* d_in, const int* in_sizes, int n_in,
                              void* d_out, int out_size) {
    const float* z   = nullptr;
    const float* emb = nullptr;
    for (int i = 0; i < n_in; i++) {
        long s = (long)in_sizes[i];
        if (s == 16777216L || s == 67108864L)   z   = (const float*)d_in[i];
        else if (s == 262144L || s == 1048576L) emb = (const float*)d_in[i];
    }
    if (!z)   z   = (const float*)d_in[0];
    if (!emb) emb = (const float*)d_in[n_in > 1 ? 1 : 0];
    float* out = (float*)d_out;

    reset_kernel<<<1, 32>>>();
    enorm_kernel<<<KCODES / 128, 128>>>(emb);
    anorm_kernel<<<NPIX / 128, 128>>>(z);
    vq_kernel<<<NPIX / BPX, THREADS>>>(z, emb, out);
    fixup_kernel<<<1024, 256>>>(z, emb, out);
}

// round 9
// speedup vs baseline: 38.3208x; 2.3434x over previous
#include <cuda_runtime.h>
#include <cstddef>

#define KCODES 1024
#define DDIM   256
#define NPIX   65536
#define THREADS 256
#define MARGIN  7.5e-5f

// ---- wide main kernel geometry ----
#define BPW 128      // pixels per block
#define TKW 128      // codes per tile
#define DCW 32       // d per chunk
#define SEW 132      // e_s row stride (128 codes + pad)
// smem layout (floats)
#define ZW_OFF  0                       // 32768
#define EW_OFF  32768                   // 4224 (32*132)
#define ENW_OFF (32768 + 4224)          // 1024
#define AW_OFF  (ENW_OFF + 1024)        // 128
#define SMEMW_FLOATS (AW_OFF + 128)     // 38144 floats = 152,576 B

__device__ float g_enorm[KCODES];
__device__ float g_A[NPIX];
__device__ int   g_nflag;
__device__ int   g_flags[NPIX];

// packed f32x2 FMA: a = x*y + a (two lanewise IEEE-rn fp32 FMAs)
#define FMA2(a, x, y) \
    asm("fma.rn.f32x2 %0, %1, %2, %0;" : "+l"(a) : "l"(x), "l"(y))
// duplicate scalar float into both halves of a u64
#define DUP2(d, s) \
    asm("mov.b64 %0, {%1,%1};" : "=l"(d) : "f"(s))

// ---------------------------------------------------------------------------
// Emulated reference row sum-of-squares (proven exact in R7/R8).
// ---------------------------------------------------------------------------
__device__ __forceinline__ float sumsq_emul(const float* x, long stride) {
    float S[8];
#pragma unroll
    for (int l = 0; l < 8; l++) S[l] = 0.f;
    for (int t = 0; t < DDIM / 8; t++) {
#pragma unroll
        for (int l = 0; l < 8; l++) {
            float v = x[(long)(8 * t + l) * stride];
            S[l] = __fadd_rn(S[l], __fmul_rn(v, v));
        }
    }
    float m0 = __fadd_rn(S[0], S[4]);
    float m1 = __fadd_rn(S[1], S[5]);
    float m2 = __fadd_rn(S[2], S[6]);
    float m3 = __fadd_rn(S[3], S[7]);
    return __fadd_rn(__fadd_rn(m0, m1), __fadd_rn(m2, m3));
}

__global__ void reset_kernel() { if (threadIdx.x == 0) g_nflag = 0; }

__global__ void enorm_kernel(const float* __restrict__ emb) {
    int c = blockIdx.x * blockDim.x + threadIdx.x;
    if (c < KCODES) g_enorm[c] = sumsq_emul(emb + (size_t)c * DDIM, 1);
}

__global__ void anorm_kernel(const float* __restrict__ z) {
    int p = blockIdx.x * blockDim.x + threadIdx.x;
    if (p < NPIX) {
        const float* zp = z + (size_t)(p >> 12) * (DDIM * 4096) + (p & 4095);
        g_A[p] = sumsq_emul(zp, 4096);
    }
}

// ---------------------------------------------------------------------------
// Main pass: packed f32x2 FMAs, 128 px/block, 8 px x 8 codes per thread.
// Tracks best + second-best; pixels with gap < MARGIN are flagged for fixup.
// ---------------------------------------------------------------------------
__global__ __launch_bounds__(THREADS, 1)
void vq_wide(const float* __restrict__ z, const float* __restrict__ emb,
             float* __restrict__ out) {
    extern __shared__ float smem[];
    float* z_s  = smem + ZW_OFF;
    float* e_s  = smem + EW_OFF;
    float* en_s = smem + ENW_OFF;
    float* A_s  = smem + AW_OFF;

    const int tid = threadIdx.x;
    const int tx  = tid & 15;    // 16 groups x 8 px  = 128 px
    const int ty  = tid >> 4;    // 16 groups x 8 cod = 128 codes/tile

    const int n0 = blockIdx.x * BPW;   // 128 | 4096 -> never crosses batch
    const float* zbase = z + (size_t)(n0 >> 12) * (DDIM * 4096) + (n0 & 4095);

    // ---- z tile [256][128], coalesced ----
#pragma unroll
    for (int it = 0; it < 32; it++) {
        int idx = it * THREADS + tid;          // 8192 float4 slots
        int d = idx >> 5, c4 = (idx & 31) << 2;
        *(float4*)(z_s + d * BPW + c4) =
            *(const float4*)(zbase + (size_t)d * 4096 + c4);
    }
    for (int i = tid; i < KCODES; i += THREADS) en_s[i] = g_enorm[i];
    if (tid < BPW) A_s[tid] = g_A[n0 + tid];
    __syncthreads();

    float A8[8];
#pragma unroll
    for (int j = 0; j < 8; j++) A8[j] = A_s[tx * 8 + j];

    float bv[8], sv[8]; int bi[8];
#pragma unroll
    for (int j = 0; j < 8; j++) { bv[j] = 3.4e38f; sv[j] = 3.4e38f; bi[j] = 0; }

    for (int k0 = 0; k0 < KCODES; k0 += TKW) {
        unsigned long long acc[4][8];          // 4 px-pairs x 8 codes
#pragma unroll
        for (int i = 0; i < 4; i++)
#pragma unroll
            for (int c = 0; c < 8; c++) acc[i][c] = 0ull;

        for (int d0 = 0; d0 < DDIM; d0 += DCW) {
            __syncthreads();
            {   // stage e chunk transposed: e_s[d][k]
                int code = tid >> 1;           // 0..127
                int q    = tid & 1;
                const float* erow = emb + (size_t)(k0 + code) * DDIM + d0;
#pragma unroll
                for (int jj = 0; jj < 4; jj++) {
                    int m = q + 2 * jj;        // float4 index 0..7
                    float4 v = *(const float4*)(erow + 4 * m);
                    e_s[(4 * m + 0) * SEW + code] = v.x;
                    e_s[(4 * m + 1) * SEW + code] = v.y;
                    e_s[(4 * m + 2) * SEW + code] = v.z;
                    e_s[(4 * m + 3) * SEW + code] = v.w;
                }
            }
            __syncthreads();

            const float* zrow = z_s + (size_t)d0 * BPW + tx * 8;
            const float* erow = e_s + ty * 8;
#pragma unroll 4
            for (int d = 0; d < DCW; d++) {
                ulonglong2 za = *(const ulonglong2*)(zrow + d * BPW);
                ulonglong2 zb = *(const ulonglong2*)(zrow + d * BPW + 4);
                float4 ea = *(const float4*)(erow + d * SEW);
                float4 eb = *(const float4*)(erow + d * SEW + 4);
                unsigned long long zz[4] = {za.x, za.y, zb.x, zb.y};
                unsigned long long ed[8];
                DUP2(ed[0], ea.x); DUP2(ed[1], ea.y);
                DUP2(ed[2], ea.z); DUP2(ed[3], ea.w);
                DUP2(ed[4], eb.x); DUP2(ed[5], eb.y);
                DUP2(ed[6], eb.z); DUP2(ed[7], eb.w);
#pragma unroll
                for (int i = 0; i < 4; i++)
#pragma unroll
                    for (int c = 0; c < 8; c++)
                        FMA2(acc[i][c], zz[i], ed[c]);
            }
        }

        // epilogue: exact reference fp32 dist; ascending k, strict '<'
#pragma unroll
        for (int c = 0; c < 8; c++) {
            int k = k0 + ty * 8 + c;
            float en = en_s[k];
#pragma unroll
            for (int i = 0; i < 4; i++) {
                float lo = __uint_as_float((unsigned)(acc[i][c] & 0xffffffffull));
                float hi = __uint_as_float((unsigned)(acc[i][c] >> 32));
                float d0v = __fadd_rn(__fsub_rn(A8[2*i],   __fmul_rn(2.0f, lo)), en);
                float d1v = __fadd_rn(__fsub_rn(A8[2*i+1], __fmul_rn(2.0f, hi)), en);
                int j0 = 2 * i, j1 = 2 * i + 1;
                if (d0v < bv[j0]) { sv[j0] = bv[j0]; bv[j0] = d0v; bi[j0] = k; }
                else if (d0v < sv[j0]) sv[j0] = d0v;
                if (d1v < bv[j1]) { sv[j1] = bv[j1]; bv[j1] = d1v; bi[j1] = k; }
                else if (d1v < sv[j1]) sv[j1] = d1v;
            }
        }
    }

    // ---- cross-thread merge (16 ty contributors per pixel) ----
    __syncthreads();
    float* rv = z_s;                     // reuse: [128][17]
    int*   ri = (int*)(z_s + 2176);
    float* rs = z_s + 4352;
#pragma unroll
    for (int j = 0; j < 8; j++) {
        int p = tx * 8 + j;
        rv[p * 17 + ty] = bv[j];
        ri[p * 17 + ty] = bi[j];
        rs[p * 17 + ty] = sv[j];
    }
    __syncthreads();
    if (tid < BPW) {
        float b = rv[tid * 17]; int x0 = ri[tid * 17]; float s = rs[tid * 17];
#pragma unroll
        for (int t = 1; t < 16; t++) {
            float v = rv[tid * 17 + t]; int x = ri[tid * 17 + t];
            float s2 = rs[tid * 17 + t];
            if (v < b || (v == b && x < x0)) { s = fminf(b, s2); b = v; x0 = x; }
            else s = fminf(s, v);
        }
        out[n0 + tid] = (float)x0;
        if (__fsub_rn(s, b) < MARGIN) {
            int idx = atomicAdd(&g_nflag, 1);
            g_flags[idx] = n0 + tid;
        }
    }
}

// ---------------------------------------------------------------------------
// Tiled fixup: 32 flagged pixels per block, embedding streamed through smem,
// double-float dots (single ascending-d chain per (px,code), as proven in R8).
// ---------------------------------------------------------------------------
#define FPX 32
#define FTK 128
#define FDC 16
#define FSE 132

__global__ __launch_bounds__(THREADS)
void fixup2(const float* __restrict__ z, const float* __restrict__ emb,
            float* __restrict__ out) {
    __shared__ float z_s[DDIM * FPX];   // 32 KB
    __shared__ float e_s[FDC * FSE];    // 8.4 KB
    __shared__ float en_s[KCODES];      // 4 KB
    __shared__ int   pl_s[FPX];
    __shared__ float A_s[FPX];

    const int tid = threadIdx.x;
    const int tx  = tid & 7;            // 8 groups x 4 px = 32
    const int ty  = tid >> 3;           // 32 groups x 4 codes = 128/tile

    for (int base = blockIdx.x * FPX; base < g_nflag; base += gridDim.x * FPX) {
        int nhere = g_nflag - base; if (nhere > FPX) nhere = FPX;
        __syncthreads();                 // protect smem reuse across chunks
        if (tid < FPX) {
            int p = g_flags[base + (tid < nhere ? tid : 0)];
            pl_s[tid] = p;
            A_s[tid]  = g_A[p];
        }
        for (int i = tid; i < KCODES; i += THREADS) en_s[i] = g_enorm[i];
        __syncthreads();
        for (int i = tid; i < DDIM * FPX; i += THREADS) {
            int d = i >> 5, q = i & 31;
            int p = pl_s[q];
            z_s[i] = z[(size_t)(p >> 12) * (DDIM * 4096)
                       + (size_t)d * 4096 + (p & 4095)];
        }
        __syncthreads();

        float bv[4]; int bi[4];
#pragma unroll
        for (int j = 0; j < 4; j++) { bv[j] = 3.4e38f; bi[j] = 0; }

        for (int k0 = 0; k0 < KCODES; k0 += FTK) {
            float hi[4][4], lo[4][4];
#pragma unroll
            for (int j = 0; j < 4; j++)
#pragma unroll
                for (int c = 0; c < 4; c++) { hi[j][c] = 0.f; lo[j][c] = 0.f; }

            for (int d0 = 0; d0 < DDIM; d0 += FDC) {
                __syncthreads();
                {   // stage e chunk [16 d][128 codes]
                    int code = tid >> 1, q = tid & 1;
                    const float* erow = emb + (size_t)(k0 + code) * DDIM + d0;
#pragma unroll
                    for (int jj = 0; jj < 2; jj++) {
                        int m = q + 2 * jj;      // 0..3
                        float4 v = *(const float4*)(erow + 4 * m);
                        e_s[(4 * m + 0) * FSE + code] = v.x;
                        e_s[(4 * m + 1) * FSE + code] = v.y;
                        e_s[(4 * m + 2) * FSE + code] = v.z;
                        e_s[(4 * m + 3) * FSE + code] = v.w;
                    }
                }
                __syncthreads();

                const float* zrow = z_s + (size_t)d0 * FPX + tx * 4;
                const float* erow = e_s + ty * 4;
#pragma unroll 2
                for (int d = 0; d < FDC; d++) {
                    float4 zz = *(const float4*)(zrow + d * FPX);
                    float4 ee = *(const float4*)(erow + d * FSE);
                    float zf[4] = {zz.x, zz.y, zz.z, zz.w};
                    float ef[4] = {ee.x, ee.y, ee.z, ee.w};
#pragma unroll
                    for (int j = 0; j < 4; j++)
#pragma unroll
                        for (int c = 0; c < 4; c++) {
                            float x = zf[j], y = ef[c];
                            float pm = __fmul_rn(x, y);
                            float e1 = fmaf(x, y, -pm);
                            float t  = __fadd_rn(hi[j][c], pm);
                            float v  = __fsub_rn(t, hi[j][c]);
                            float e2 = __fadd_rn(
                                __fsub_rn(hi[j][c], __fsub_rn(t, v)),
                                __fsub_rn(pm, v));
                            hi[j][c] = t;
                            lo[j][c] = __fadd_rn(lo[j][c], __fadd_rn(e1, e2));
                        }
                }
            }
#pragma unroll
            for (int c = 0; c < 4; c++) {
                int k = k0 + ty * 4 + c;
                float en = en_s[k];
#pragma unroll
                for (int j = 0; j < 4; j++) {
                    float M  = __fadd_rn(hi[j][c], lo[j][c]);
                    float dv = __fadd_rn(
                        __fsub_rn(A_s[tx * 4 + j], __fmul_rn(2.0f, M)), en);
                    if (dv < bv[j]) { bv[j] = dv; bi[j] = k; }
                }
            }
        }

        // cross-thread merge (32 ty per pixel), tie -> smallest index
        __syncthreads();
        float* rv = z_s;                   // reuse: [32][33]
        int*   ri = (int*)(z_s + 1056);
#pragma unroll
        for (int j = 0; j < 4; j++) {
            int p = tx * 4 + j;
            rv[p * 33 + ty] = bv[j];
            ri[p * 33 + ty] = bi[j];
        }
        __syncthreads();
        if (tid < nhere) {
            float b = rv[tid * 33]; int x0 = ri[tid * 33];
#pragma unroll
            for (int t = 1; t < 32; t++) {
                float v = rv[tid * 33 + t]; int x = ri[tid * 33 + t];
                if (v < b || (v == b && x < x0)) { b = v; x0 = x; }
            }
            out[pl_s[tid]] = (float)x0;
        }
    }
}

// ---------------------------------------------------------------------------
extern "C" void kernel_launch(void* const* d_in, const int* in_sizes, int n_in,
                              void* d_out, int out_size) {
    const float* z   = nullptr;
    const float* emb = nullptr;
    for (int i = 0; i < n_in; i++) {
        long s = (long)in_sizes[i];
        if (s == 16777216L || s == 67108864L)   z   = (const float*)d_in[i];
        else if (s == 262144L || s == 1048576L) emb = (const float*)d_in[i];
    }
    if (!z)   z   = (const float*)d_in[0];
    if (!emb) emb = (const float*)d_in[n_in > 1 ? 1 : 0];
    float* out = (float*)d_out;

    reset_kernel<<<1, 32>>>();
    enorm_kernel<<<KCODES / 128, 128>>>(emb);
    anorm_kernel<<<NPIX / 128, 128>>>(z);

    size_t smw = (size_t)SMEMW_FLOATS * sizeof(float);
    cudaFuncSetAttribute(vq_wide, cudaFuncAttributeMaxDynamicSharedMemorySize,
                         (int)smw);
    vq_wide<<<NPIX / BPW, THREADS, smw>>>(z, emb, out);
    fixup2<<<256, THREADS>>>(z, emb, out);
}